// round 11
// baseline (speedup 1.0000x reference)
#include <cuda_runtime.h>
#include <cuda_bf16.h>
#include <cstdint>

#define B_DIM 32
#define C_DIM 512
#define N_DIM 1024   // H*W

// ---------------- device scratch (allocation-free) --------------------------
__device__ __align__(16) unsigned short g_wvh[64 * 512];    // Wv^T hi  [d][c]
__device__ __align__(16) unsigned short g_wvl[64 * 512];    // Wv^T lo
__device__ __align__(16) unsigned short g_wph[512 * 512];   // Wp^T hi  [c2][c]
__device__ __align__(16) unsigned short g_wpl[512 * 512];   // Wp^T lo
__device__ float g_bv[64];
__device__ __align__(16) unsigned g_vh[B_DIM * 1024 * 32];  // v hi bf16 pairs [b][n][d/2]
__device__ __align__(16) unsigned g_vl[B_DIM * 1024 * 32];  // v lo
__device__ int g_flag[B_DIM];     // per-batch producer count (self-resetting)
__device__ int g_cons[B_DIM];     // per-batch consumer count (self-resetting)
__device__ int g_wready;          // weight-prep arrival counter (self-resetting)
__device__ int g_done;            // CTA completion counter (self-resetting)

// ---------------- helpers ----------------------------------------------------
__device__ __forceinline__ unsigned smem_u32(const void* p) {
    unsigned a;
    asm("{ .reg .u64 t; cvta.to.shared.u64 t, %1; cvt.u32.u64 %0, t; }" : "=r"(a) : "l"(p));
    return a;
}
__device__ __forceinline__ void ldm_x4(unsigned* d, unsigned addr) {
    asm volatile("ldmatrix.sync.aligned.m8n8.x4.shared.b16 {%0,%1,%2,%3}, [%4];"
                 : "=r"(d[0]), "=r"(d[1]), "=r"(d[2]), "=r"(d[3]) : "r"(addr));
}
__device__ __forceinline__ void mma_bf16(float* c, const unsigned* a, const unsigned* b) {
    asm volatile(
        "mma.sync.aligned.m16n8k16.row.col.f32.bf16.bf16.f32 "
        "{%0,%1,%2,%3}, {%4,%5,%6,%7}, {%8,%9}, {%0,%1,%2,%3};"
        : "+f"(c[0]), "+f"(c[1]), "+f"(c[2]), "+f"(c[3])
        : "r"(a[0]), "r"(a[1]), "r"(a[2]), "r"(a[3]), "r"(b[0]), "r"(b[1]));
}
__device__ __forceinline__ void cp16(unsigned dst, const void* src) {
    asm volatile("cp.async.cg.shared.global [%0], [%1], 16;" :: "r"(dst), "l"(src));
}
__device__ __forceinline__ void cp_commit() { asm volatile("cp.async.commit_group;" ::: "memory"); }
__device__ __forceinline__ void cp_wait0()  { asm volatile("cp.async.wait_group 0;" ::: "memory"); }

__device__ __forceinline__ void cvt_split_pair(float f0, float f1, unsigned& h, unsigned& l) {
    asm("cvt.rn.bf16x2.f32 %0, %1, %2;" : "=r"(h) : "f"(f1), "f"(f0));
    float r0 = f0 - __uint_as_float(h << 16);
    float r1 = f1 - __uint_as_float(h & 0xffff0000u);
    asm("cvt.rn.bf16x2.f32 %0, %1, %2;" : "=r"(l) : "f"(r1), "f"(r0));
}

// stage layout (pitch 144B): Ah[128] @0 | Al @18432 | Bh[64] @36864 | Bl @46080
#define S_AL  18432
#define S_B   36864
#define S_BL  9216
#define S_STG 55296
#define FUSED_SMEM (2 * S_STG)   // 110592 -> 2 CTAs/SM

// ---------------- warp MMA fragment offsets (pitch 144B) ---------------------
struct Frag { unsigned aoff[2]; unsigned boff[2]; };

__device__ __forceinline__ Frag make_frag(int lane, int mw, int nw) {
    Frag fr;
    const int j4 = lane >> 3, r8 = lane & 7;
    #pragma unroll
    for (int mi = 0; mi < 2; ++mi)
        fr.aoff[mi] = (mw * 32 + mi * 16 + (j4 & 1) * 8 + r8) * 144 + (j4 >> 1) * 16;
    const int g2 = (lane >> 4) & 1, c8 = (lane >> 3) & 1;
    #pragma unroll
    for (int j2 = 0; j2 < 2; ++j2)
        fr.boff[j2] = S_B + (nw * 32 + j2 * 16 + g2 * 8 + r8) * 144 + c8 * 16;
    return fr;
}

template<int K0, int K1>
__device__ __forceinline__ void mma_stage(unsigned base, const Frag& fr, float C[2][4][4]) {
    #pragma unroll
    for (int ks = K0; ks < K1; ++ks) {
        unsigned ah[2][4], al[2][4], bh[2][4], bl[2][4];
        #pragma unroll
        for (int mi = 0; mi < 2; ++mi) {
            ldm_x4(ah[mi], base + fr.aoff[mi] + ks * 32);
            ldm_x4(al[mi], base + fr.aoff[mi] + ks * 32 + S_AL);
        }
        #pragma unroll
        for (int j2 = 0; j2 < 2; ++j2) {
            ldm_x4(bh[j2], base + fr.boff[j2] + ks * 32);
            ldm_x4(bl[j2], base + fr.boff[j2] + ks * 32 + S_BL);
        }
        #pragma unroll
        for (int mi = 0; mi < 2; ++mi)
            #pragma unroll
            for (int ni = 0; ni < 4; ++ni) {
                const unsigned* bhp = &bh[ni >> 1][(ni & 1) * 2];
                const unsigned* blp = &bl[ni >> 1][(ni & 1) * 2];
                mma_bf16(C[mi][ni], ah[mi], bhp);
                mma_bf16(C[mi][ni], ah[mi], blp);
                mma_bf16(C[mi][ni], al[mi], bhp);
            }
    }
}

// ---------------- prep slice (runs inside fused kernel) ----------------------
__device__ __forceinline__ void prep_body(const float* __restrict__ Wqkv,
                                          const float* __restrict__ bqkv,
                                          const float* __restrict__ Wp,
                                          char* smem, int bid, int tid) {
    if (bid < 128) {
        int idx = bid * 256 + tid;                 // 32768
        int d = idx & 63, c = idx >> 6;
        const float* p = Wqkv + (size_t)c * 1536 + 1024 + d;
        float s = 0.f;
        #pragma unroll
        for (int h = 0; h < 8; ++h) s += p[h * 64];
        s *= 0.125f;
        __nv_bfloat16 hi = __float2bfloat16(s);
        __nv_bfloat16 lo = __float2bfloat16(s - __bfloat162float(hi));
        g_wvh[d * 512 + c] = *(unsigned short*)&hi;
        g_wvl[d * 512 + c] = *(unsigned short*)&lo;
        if (idx < 64) {
            float t = 0.f;
            #pragma unroll
            for (int h = 0; h < 8; ++h) t += bqkv[1024 + h * 64 + idx];
            g_bv[idx] = t * 0.125f;
        }
    }
    // every CTA: one 32x32 Wp transpose tile
    float (*th)[33] = (float(*)[33])smem;
    float (*tl)[33] = th + 32;
    int c0 = (bid & 15) * 32, c20 = (bid >> 4) * 32;
    int tx = tid & 31, ty = tid >> 5;              // (32, 8)
    #pragma unroll
    for (int i = 0; i < 4; ++i) {
        int c = c0 + ty + i * 8;
        float s = Wp[(size_t)c * 512 + c20 + tx];
        float hi = __bfloat162float(__float2bfloat16(s));
        th[ty + i * 8][tx] = hi;
        tl[ty + i * 8][tx] = s - hi;
    }
    __syncthreads();
    #pragma unroll
    for (int i = 0; i < 4; ++i) {
        int c2 = c20 + ty + i * 8;
        __nv_bfloat16 hb = __float2bfloat16(th[tx][ty + i * 8]);
        __nv_bfloat16 lb = __float2bfloat16(tl[tx][ty + i * 8]);
        g_wph[(size_t)c2 * 512 + c0 + tx] = *(unsigned short*)&hb;
        g_wpl[(size_t)c2 * 512 + c0 + tx] = *(unsigned short*)&lb;
    }
}

// -------------------- GEMM1 body: tile 128(n) x 64(d), K-chunk 64 x 8 -------
__device__ __forceinline__ void gemm1_body(const float* __restrict__ x,
                                           char* smem, int b, int n0) {
    const int tid = threadIdx.x, lane = tid & 31, wid = tid >> 5;
    const int mw = wid >> 1, nw = wid & 1;
    const unsigned sb = smem_u32(smem);
    const Frag fr = make_frag(lane, mw, nw);

    const int m_ld = tid & 127, kb0 = tid >> 7;    // kblocks kb0 + 2i within half
    const float* xb = x + (size_t)b * (C_DIM * N_DIM) + n0;

    float C[2][4][4] = {};
    float f[2][8];

    auto ldg_half = [&](int kc, int h) {
        const float* xc = xb + (size_t)(kc * 64 + h * 32) * N_DIM;
        #pragma unroll
        for (int i = 0; i < 2; ++i) {
            int k0 = (kb0 + 2 * i) * 8;
            #pragma unroll
            for (int j = 0; j < 8; ++j)
                f[i][j] = xc[(size_t)(k0 + j) * N_DIM + m_ld];
        }
    };
    auto cvt_half = [&](int st, int h) {
        char* base = smem + st * S_STG;
        #pragma unroll
        for (int i = 0; i < 2; ++i) {
            unsigned hh[4], ll[4];
            #pragma unroll
            for (int p = 0; p < 4; ++p)
                cvt_split_pair(f[i][2 * p], f[i][2 * p + 1], hh[p], ll[p]);
            unsigned off = m_ld * 144 + h * 64 + (kb0 + 2 * i) * 16;
            *(uint4*)(base + off) = make_uint4(hh[0], hh[1], hh[2], hh[3]);
            *(uint4*)(base + S_AL + off) = make_uint4(ll[0], ll[1], ll[2], ll[3]);
        }
    };
    auto issueB = [&](int kc, int st) {
        unsigned stb = sb + st * S_STG + S_B;
        #pragma unroll
        for (int i = 0; i < 2; ++i) {
            int idx = tid + i * 256;               // 512 quads
            int r = idx >> 3, q = idx & 7;
            size_t s = (size_t)r * 512 + kc * 64 + q * 8;
            unsigned dst = stb + r * 144 + q * 16;
            cp16(dst, g_wvh + s);
            cp16(dst + S_BL, g_wvl + s);
        }
        cp_commit();
    };

    // prologue: stage 0 A fully converted; first weights copy; chunk1 h0 in regs
    ldg_half(0, 0);
    cvt_half(0, 0);
    ldg_half(0, 1);
    cvt_half(0, 1);
    ldg_half(1, 0);

    // weight-prep wait (producers overlap the wait with the x work above)
    if (tid == 0) {
        volatile int* w = &g_wready;
        while (*w < 256) __nanosleep(64);
    }
    __syncthreads();
    __threadfence();

    issueB(0, 0);

    for (int kc = 0; kc < 8; ++kc) {
        const int st = kc & 1, nst = st ^ 1;
        cp_wait0();
        __syncthreads();
        if (kc < 7) { cvt_half(nst, 0); issueB(kc + 1, nst); ldg_half(kc + 1, 1); }
        mma_stage<0, 2>(sb + st * S_STG, fr, C);
        if (kc < 7) { cvt_half(nst, 1); if (kc < 6) ldg_half(kc + 2, 0); }
        mma_stage<2, 4>(sb + st * S_STG, fr, C);
    }

    // epilogue: add bias, split, store v
    const int gr = lane >> 2, gc2 = (lane & 3) * 2;
    #pragma unroll
    for (int mi = 0; mi < 2; ++mi) {
        int m = n0 + mw * 32 + mi * 16 + gr;
        unsigned base0 = (unsigned)(b * 1024 + m) * 32u;
        unsigned base1 = base0 + 8 * 32;
        #pragma unroll
        for (int ni = 0; ni < 4; ++ni) {
            int d = nw * 32 + ni * 8 + gc2;
            float bv0 = g_bv[d], bv1 = g_bv[d + 1];
            unsigned h, l;
            cvt_split_pair(C[mi][ni][0] + bv0, C[mi][ni][1] + bv1, h, l);
            g_vh[base0 + (d >> 1)] = h;
            g_vl[base0 + (d >> 1)] = l;
            cvt_split_pair(C[mi][ni][2] + bv0, C[mi][ni][3] + bv1, h, l);
            g_vh[base1 + (d >> 1)] = h;
            g_vl[base1 + (d >> 1)] = l;
        }
    }

    __threadfence();
    __syncthreads();
    if (tid == 0) atomicAdd(&g_flag[b], 1);
}

// -------------------- GEMM2 body: tile 128(r) x 64(c2), K-chunk 64 x 8 ------
__device__ __forceinline__ void gemm2_body(const float* __restrict__ bp,
                                           float* __restrict__ out,
                                           char* smem, int b, int c20) {
    const int tid = threadIdx.x, lane = tid & 31, wid = tid >> 5;
    const int mw = wid >> 1, nw = wid & 1;
    const unsigned sb = smem_u32(smem);
    const Frag fr = make_frag(lane, mw, nw);

    // acquire: wait for all 8 producer CTAs of this batch
    if (tid == 0) {
        volatile int* fl = &g_flag[b];
        while (*fl < 8) __nanosleep(64);
        int old = atomicAdd(&g_cons[b], 1);
        if (old == 7) { g_flag[b] = 0; g_cons[b] = 0; }   // last consumer resets
    }
    __syncthreads();
    __threadfence();

    const unsigned short* vhb = (const unsigned short*)g_vh + (size_t)b * 65536;
    const unsigned short* vlb = (const unsigned short*)g_vl + (size_t)b * 65536;

    float C[2][4][4] = {};

    auto issue = [&](int kc, int st) {
        unsigned stb = sb + st * S_STG;
        #pragma unroll
        for (int i = 0; i < 4; ++i) {
            int idx = tid + i * 256;               // 1024 quads (A: 128 rows x 8)
            int r = idx >> 3, q = idx & 7;
            size_t s = (size_t)r * 512 + kc * 64 + q * 8;
            unsigned off = stb + r * 144 + q * 16;
            cp16(off, vhb + s);
            cp16(off + S_AL, vlb + s);
        }
        #pragma unroll
        for (int i = 0; i < 2; ++i) {
            int idx = tid + i * 256;               // 512 quads (B: 64 rows x 8)
            int r = idx >> 3, q = idx & 7;
            size_t s = (size_t)(c20 + r) * 512 + kc * 64 + q * 8;
            unsigned off = stb + S_B + r * 144 + q * 16;
            cp16(off, g_wph + s);
            cp16(off + S_BL, g_wpl + s);
        }
        cp_commit();
    };

    issue(0, 0);

    for (int kc = 0; kc < 8; ++kc) {
        const int st = kc & 1;
        cp_wait0();
        __syncthreads();
        if (kc < 7) issue(kc + 1, st ^ 1);
        mma_stage<0, 2>(sb + st * S_STG, fr, C);
        mma_stage<2, 4>(sb + st * S_STG, fr, C);
    }
    __syncthreads();

    // epilogue: stage to smem [c2][r] with bias, then coalesced x8 broadcast
    float* Cs = (float*)smem;      // [64][132] floats = 33792 B <= 110592
    const int gr = lane >> 2, gc2 = (lane & 3) * 2;
    #pragma unroll
    for (int mi = 0; mi < 2; ++mi) {
        int r = mw * 32 + mi * 16 + gr;
        #pragma unroll
        for (int ni = 0; ni < 4; ++ni) {
            int c2l = nw * 32 + ni * 8 + gc2;
            float b0 = __ldg(bp + c20 + c2l), b1 = __ldg(bp + c20 + c2l + 1);
            Cs[c2l * 132 + r]           = C[mi][ni][0] + b0;
            Cs[(c2l + 1) * 132 + r]     = C[mi][ni][1] + b1;
            Cs[c2l * 132 + r + 8]       = C[mi][ni][2] + b0;
            Cs[(c2l + 1) * 132 + r + 8] = C[mi][ni][3] + b1;
        }
    }
    __syncthreads();

    float* ob = out + (size_t)b * (C_DIM * N_DIM) + (size_t)c20 * N_DIM;
    const int f4 = tid & 31, sub = tid >> 5;
    #pragma unroll 4
    for (int i = 0; i < 64; ++i) {
        int rowid = i * 8 + sub;
        int c2l = rowid >> 3, mrep = rowid & 7;
        float4 v = *(float4*)&Cs[c2l * 132 + f4 * 4];
        *(float4*)(ob + (size_t)c2l * N_DIM + mrep * 128 + f4 * 4) = v;
    }
}

// ---------------------------------------------------------------------------
// Single fused persistent kernel: 256 CTAs x 256 threads, 2 CTAs/SM (all
// resident). Each CTA: prep slice -> arrive -> produce gemm1 tile -> flag ->
// consume gemm2 tile. Counters self-reset for graph replay.
// ---------------------------------------------------------------------------
__global__ void __launch_bounds__(256, 2) fused_all(const float* __restrict__ x,
                                                    const float* __restrict__ Wqkv,
                                                    const float* __restrict__ bqkv,
                                                    const float* __restrict__ Wp,
                                                    const float* __restrict__ bp,
                                                    float* __restrict__ out) {
    extern __shared__ char smem[];
    const int bid = blockIdx.x, tid = threadIdx.x;
    const int b = bid >> 3, t8 = bid & 7;

    prep_body(Wqkv, bqkv, Wp, smem, bid, tid);
    __threadfence();
    __syncthreads();
    if (tid == 0) atomicAdd(&g_wready, 1);

    gemm1_body(x, smem, b, t8 * 128);
    gemm2_body(bp, out, smem, b, t8 * 64);

    if (tid == 0) {
        int old = atomicAdd(&g_done, 1);
        if (old == 255) { g_done = 0; g_wready = 0; }   // last CTA resets globals
    }
}

// ---------------------------------------------------------------------------
extern "C" void kernel_launch(void* const* d_in, const int* in_sizes, int n_in,
                              void* d_out, int out_size) {
    const float* x    = (const float*)d_in[0];
    const float* Wqkv = (const float*)d_in[1];
    const float* bqkv = (const float*)d_in[2];
    const float* Wp   = (const float*)d_in[3];
    const float* bp   = (const float*)d_in[4];
    float* out = (float*)d_out;

    cudaFuncSetAttribute(fused_all, cudaFuncAttributeMaxDynamicSharedMemorySize, FUSED_SMEM);
    fused_all<<<256, 256, FUSED_SMEM>>>(x, Wqkv, bqkv, Wp, bp, out);
}

// round 12
// speedup vs baseline: 1.4025x; 1.4025x over previous
#include <cuda_runtime.h>
#include <cuda_fp16.h>
#include <cstdint>

#define B_DIM 32
#define C_DIM 512
#define N_DIM 1024   // H*W

// ---------------- device scratch (allocation-free) --------------------------
__device__ __align__(16) unsigned short g_wv[64 * 512];     // Wv^T fp16 [d][c]
__device__ __align__(16) unsigned short g_wp[512 * 512];    // Wp^T fp16 [c2][c]
__device__ float g_bv[64];
__device__ __align__(16) unsigned g_v[B_DIM * 1024 * 32];   // v fp16 pairs [b][n][d/2]
__device__ int g_flag[B_DIM];                               // per-batch producer count

// ---------------- helpers ----------------------------------------------------
__device__ __forceinline__ unsigned smem_u32(const void* p) {
    unsigned a;
    asm("{ .reg .u64 t; cvta.to.shared.u64 t, %1; cvt.u32.u64 %0, t; }" : "=r"(a) : "l"(p));
    return a;
}
__device__ __forceinline__ void ldm_x4(unsigned* d, unsigned addr) {
    asm volatile("ldmatrix.sync.aligned.m8n8.x4.shared.b16 {%0,%1,%2,%3}, [%4];"
                 : "=r"(d[0]), "=r"(d[1]), "=r"(d[2]), "=r"(d[3]) : "r"(addr));
}
__device__ __forceinline__ void mma_f16(float* c, const unsigned* a, const unsigned* b) {
    asm volatile(
        "mma.sync.aligned.m16n8k16.row.col.f32.f16.f16.f32 "
        "{%0,%1,%2,%3}, {%4,%5,%6,%7}, {%8,%9}, {%0,%1,%2,%3};"
        : "+f"(c[0]), "+f"(c[1]), "+f"(c[2]), "+f"(c[3])
        : "r"(a[0]), "r"(a[1]), "r"(a[2]), "r"(a[3]), "r"(b[0]), "r"(b[1]));
}
__device__ __forceinline__ void cp16(unsigned dst, const void* src) {
    asm volatile("cp.async.cg.shared.global [%0], [%1], 16;" :: "r"(dst), "l"(src));
}
__device__ __forceinline__ void cp_commit() { asm volatile("cp.async.commit_group;" ::: "memory"); }
__device__ __forceinline__ void cp_wait0()  { asm volatile("cp.async.wait_group 0;" ::: "memory"); }

// pack (f0, f1) -> f16x2 word (lo half = f0)
__device__ __forceinline__ unsigned cvt_f16x2(float f0, float f1) {
    unsigned h;
    asm("cvt.rn.f16x2.f32 %0, %1, %2;" : "=r"(h) : "f"(f1), "f"(f0));
    return h;
}

// stage layout (pitch 144B): A[128 rows] @0 (18432) | B[64 rows] @18432 (9216)
#define H_B   18432
#define H_STG 27648
#define FUSED_SMEM (2 * H_STG)   // 55296

// ---------------------------------------------------------------------------
// prep (single launch): blocks [0,128) -> Wv^T fp16 + bias; [128,384) -> Wp^T
// Zeroes per-batch flags each replay.
// ---------------------------------------------------------------------------
__global__ void prep_all(const float* __restrict__ Wqkv, const float* __restrict__ bqkv,
                         const float* __restrict__ Wp) {
    int bid = blockIdx.x, tid = threadIdx.x;
    if (bid == 0 && tid < B_DIM) g_flag[tid] = 0;
    if (bid < 128) {
        int idx = bid * 256 + tid;                 // 32768
        int d = idx & 63, c = idx >> 6;
        const float* p = Wqkv + (size_t)c * 1536 + 1024 + d;
        float s = 0.f;
        #pragma unroll
        for (int h = 0; h < 8; ++h) s += p[h * 64];
        s *= 0.125f;
        __half hv = __float2half_rn(s);
        g_wv[d * 512 + c] = *(unsigned short*)&hv;
        if (idx < 64) {
            float t = 0.f;
            #pragma unroll
            for (int h = 0; h < 8; ++h) t += bqkv[1024 + h * 64 + idx];
            g_bv[idx] = t * 0.125f;
        }
    } else {
        __shared__ float ts[32][33];
        int t = bid - 128;                          // 256 tiles
        int c0 = (t & 15) * 32, c20 = (t >> 4) * 32;
        int tx = tid & 31, ty = tid >> 5;           // (32, 8)
        #pragma unroll
        for (int i = 0; i < 4; ++i) {
            int c = c0 + ty + i * 8;
            ts[ty + i * 8][tx] = Wp[(size_t)c * 512 + c20 + tx];
        }
        __syncthreads();
        #pragma unroll
        for (int i = 0; i < 4; ++i) {
            int c2 = c20 + ty + i * 8;
            __half hb = __float2half_rn(ts[tx][ty + i * 8]);
            g_wp[(size_t)c2 * 512 + c0 + tx] = *(unsigned short*)&hb;
        }
    }
}

// ---------------- warp MMA fragment offsets (pitch 144B) ---------------------
struct Frag { unsigned aoff[2]; unsigned boff[2]; };

__device__ __forceinline__ Frag make_frag(int lane, int mw, int nw) {
    Frag fr;
    const int j4 = lane >> 3, r8 = lane & 7;
    #pragma unroll
    for (int mi = 0; mi < 2; ++mi)
        fr.aoff[mi] = (mw * 32 + mi * 16 + (j4 & 1) * 8 + r8) * 144 + (j4 >> 1) * 16;
    const int g2 = (lane >> 4) & 1, c8 = (lane >> 3) & 1;
    #pragma unroll
    for (int j2 = 0; j2 < 2; ++j2)
        fr.boff[j2] = H_B + (nw * 32 + j2 * 16 + g2 * 8 + r8) * 144 + c8 * 16;
    return fr;
}

template<int K0, int K1>
__device__ __forceinline__ void mma_stage(unsigned base, const Frag& fr, float C[2][4][4]) {
    #pragma unroll
    for (int ks = K0; ks < K1; ++ks) {
        unsigned a[2][4], b[2][4];
        #pragma unroll
        for (int mi = 0; mi < 2; ++mi)
            ldm_x4(a[mi], base + fr.aoff[mi] + ks * 32);
        #pragma unroll
        for (int j2 = 0; j2 < 2; ++j2)
            ldm_x4(b[j2], base + fr.boff[j2] + ks * 32);
        #pragma unroll
        for (int mi = 0; mi < 2; ++mi)
            #pragma unroll
            for (int ni = 0; ni < 4; ++ni)
                mma_f16(C[mi][ni], a[mi], &b[ni >> 1][(ni & 1) * 2]);
    }
}

// -------------------- GEMM1 body: tile 128(n) x 64(d), K-chunk 64 x 8 -------
__device__ __forceinline__ void gemm1_body(const float* __restrict__ x,
                                           char* smem, int b, int n0) {
    const int tid = threadIdx.x, lane = tid & 31, wid = tid >> 5;
    const int mw = wid >> 1, nw = wid & 1;
    const unsigned sb = smem_u32(smem);
    const Frag fr = make_frag(lane, mw, nw);

    const int m_ld = tid & 127, kb0 = tid >> 7;    // kblocks kb0 + 2i within half
    const float* xb = x + (size_t)b * (C_DIM * N_DIM) + n0;

    float C[2][4][4] = {};
    float f[2][8];

    auto ldg_half = [&](int kc, int h) {
        const float* xc = xb + (size_t)(kc * 64 + h * 32) * N_DIM;
        #pragma unroll
        for (int i = 0; i < 2; ++i) {
            int k0 = (kb0 + 2 * i) * 8;
            #pragma unroll
            for (int j = 0; j < 8; ++j)
                f[i][j] = xc[(size_t)(k0 + j) * N_DIM + m_ld];
        }
    };
    auto cvt_half = [&](int st, int h) {
        char* base = smem + st * H_STG;
        #pragma unroll
        for (int i = 0; i < 2; ++i) {
            unsigned w0 = cvt_f16x2(f[i][0], f[i][1]);
            unsigned w1 = cvt_f16x2(f[i][2], f[i][3]);
            unsigned w2 = cvt_f16x2(f[i][4], f[i][5]);
            unsigned w3 = cvt_f16x2(f[i][6], f[i][7]);
            unsigned off = m_ld * 144 + h * 64 + (kb0 + 2 * i) * 16;
            *(uint4*)(base + off) = make_uint4(w0, w1, w2, w3);
        }
    };
    auto issueB = [&](int kc, int st) {
        unsigned stb = sb + st * H_STG + H_B;
        #pragma unroll
        for (int i = 0; i < 2; ++i) {
            int idx = tid + i * 256;               // 512 quads: 64 rows x 8
            int r = idx >> 3, q = idx & 7;
            size_t s = (size_t)r * 512 + kc * 64 + q * 8;
            cp16(stb + r * 144 + q * 16, g_wv + s);
        }
        cp_commit();
    };

    // prologue: stage 0 = chunk 0 full; f = chunk 1 half 0
    ldg_half(0, 0);
    cvt_half(0, 0);
    ldg_half(0, 1);
    cvt_half(0, 1);
    ldg_half(1, 0);
    issueB(0, 0);

    for (int kc = 0; kc < 8; ++kc) {
        const int st = kc & 1, nst = st ^ 1;
        cp_wait0();
        __syncthreads();
        if (kc < 7) { cvt_half(nst, 0); issueB(kc + 1, nst); ldg_half(kc + 1, 1); }
        mma_stage<0, 2>(sb + st * H_STG, fr, C);
        if (kc < 7) { cvt_half(nst, 1); if (kc < 6) ldg_half(kc + 2, 0); }
        mma_stage<2, 4>(sb + st * H_STG, fr, C);
    }

    // epilogue: add bias, convert to fp16, store v
    const int gr = lane >> 2, gc2 = (lane & 3) * 2;
    #pragma unroll
    for (int mi = 0; mi < 2; ++mi) {
        int m = n0 + mw * 32 + mi * 16 + gr;
        unsigned base0 = (unsigned)(b * 1024 + m) * 32u;
        unsigned base1 = base0 + 8 * 32;
        #pragma unroll
        for (int ni = 0; ni < 4; ++ni) {
            int d = nw * 32 + ni * 8 + gc2;
            float bv0 = g_bv[d], bv1 = g_bv[d + 1];
            g_v[base0 + (d >> 1)] = cvt_f16x2(C[mi][ni][0] + bv0, C[mi][ni][1] + bv1);
            g_v[base1 + (d >> 1)] = cvt_f16x2(C[mi][ni][2] + bv0, C[mi][ni][3] + bv1);
        }
    }

    __threadfence();
    __syncthreads();
    if (tid == 0) atomicAdd(&g_flag[b], 1);
}

// -------------------- GEMM2 body: tile 128(r) x 64(c2), K-chunk 64 x 8 ------
__device__ __forceinline__ void gemm2_body(const float* __restrict__ bp,
                                           float* __restrict__ out,
                                           char* smem, int b, int c20) {
    const int tid = threadIdx.x, lane = tid & 31, wid = tid >> 5;
    const int mw = wid >> 1, nw = wid & 1;
    const unsigned sb = smem_u32(smem);
    const Frag fr = make_frag(lane, mw, nw);

    // acquire: wait for all 8 producer CTAs of this batch
    if (tid == 0) {
        volatile int* fl = &g_flag[b];
        while (*fl < 8) __nanosleep(64);
    }
    __syncthreads();
    __threadfence();

    const unsigned short* vb = (const unsigned short*)g_v + (size_t)b * 65536;

    float C[2][4][4] = {};

    auto issue = [&](int kc, int st) {
        unsigned stb = sb + st * H_STG;
        #pragma unroll
        for (int i = 0; i < 4; ++i) {
            int idx = tid + i * 256;               // 1024 quads (A: 128 rows x 8)
            int r = idx >> 3, q = idx & 7;
            size_t s = (size_t)r * 512 + kc * 64 + q * 8;
            cp16(stb + r * 144 + q * 16, vb + s);
        }
        #pragma unroll
        for (int i = 0; i < 2; ++i) {
            int idx = tid + i * 256;               // 512 quads (B: 64 rows x 8)
            int r = idx >> 3, q = idx & 7;
            size_t s = (size_t)(c20 + r) * 512 + kc * 64 + q * 8;
            cp16(stb + H_B + r * 144 + q * 16, g_wp + s);
        }
        cp_commit();
    };

    issue(0, 0);

    for (int kc = 0; kc < 8; ++kc) {
        const int st = kc & 1;
        cp_wait0();
        __syncthreads();
        if (kc < 7) issue(kc + 1, st ^ 1);
        mma_stage<0, 4>(sb + st * H_STG, fr, C);
    }
    __syncthreads();

    // epilogue: stage to smem [c2][r] with bias, then coalesced x8 broadcast
    float* Cs = (float*)smem;      // [64][132] floats = 33792 B <= 55296
    const int gr = lane >> 2, gc2 = (lane & 3) * 2;
    #pragma unroll
    for (int mi = 0; mi < 2; ++mi) {
        int r = mw * 32 + mi * 16 + gr;
        #pragma unroll
        for (int ni = 0; ni < 4; ++ni) {
            int c2l = nw * 32 + ni * 8 + gc2;
            float b0 = __ldg(bp + c20 + c2l), b1 = __ldg(bp + c20 + c2l + 1);
            Cs[c2l * 132 + r]           = C[mi][ni][0] + b0;
            Cs[(c2l + 1) * 132 + r]     = C[mi][ni][1] + b1;
            Cs[c2l * 132 + r + 8]       = C[mi][ni][2] + b0;
            Cs[(c2l + 1) * 132 + r + 8] = C[mi][ni][3] + b1;
        }
    }
    __syncthreads();

    float* ob = out + (size_t)b * (C_DIM * N_DIM) + (size_t)c20 * N_DIM;
    const int f4 = tid & 31, sub = tid >> 5;
    #pragma unroll 4
    for (int i = 0; i < 64; ++i) {
        int rowid = i * 8 + sub;                   // 512 row-writes
        int c2l = rowid >> 3, mrep = rowid & 7;
        float4 v = *(float4*)&Cs[c2l * 132 + f4 * 4];
        *(float4*)(ob + (size_t)c2l * N_DIM + mrep * 128 + f4 * 4) = v;
    }
}

// ---------------------------------------------------------------------------
// Persistent fused kernel: 256 CTAs x 256 threads, 2 CTAs/SM (all resident).
// CTA i: produce gemm1 tile (b=i>>3, n0=(i&7)*128), then consume gemm2 tile
// (b=i>>3, c20=(i&7)*64). Producers never wait -> deadlock-free.
// ---------------------------------------------------------------------------
__global__ void __launch_bounds__(256, 2) fused_mma(const float* __restrict__ x,
                                                    const float* __restrict__ bp,
                                                    float* __restrict__ out) {
    extern __shared__ char smem[];
    const int bid = blockIdx.x;
    const int b = bid >> 3, t8 = bid & 7;
    gemm1_body(x, smem, b, t8 * 128);
    gemm2_body(bp, out, smem, b, t8 * 64);
}

// ---------------------------------------------------------------------------
extern "C" void kernel_launch(void* const* d_in, const int* in_sizes, int n_in,
                              void* d_out, int out_size) {
    const float* x    = (const float*)d_in[0];
    const float* Wqkv = (const float*)d_in[1];
    const float* bqkv = (const float*)d_in[2];
    const float* Wp   = (const float*)d_in[3];
    const float* bp   = (const float*)d_in[4];
    float* out = (float*)d_out;

    cudaFuncSetAttribute(fused_mma, cudaFuncAttributeMaxDynamicSharedMemorySize, FUSED_SMEM);

    prep_all<<<384, 256>>>(Wqkv, bqkv, Wp);
    fused_mma<<<256, 256, FUSED_SMEM>>>(x, bp, out);
}